// round 16
// baseline (speedup 1.0000x reference)
#include <cuda_runtime.h>
#include <cuda_fp16.h>
#include <math.h>

#define N_NODES 100000
#define N_EDGES 1000000
#define D 128
#define NEG_SLOPE 0.01f

// 8-byte packet of 4 halves (one lane's slice of a row)
struct __align__(8) half4 { __half2 a, b; };

// -------- scratch (device globals; no allocation allowed) --------
__device__ float g_el[N_NODES];
__device__ float g_er[N_NODES];
__device__ float g_s [N_NODES];           // per-dst sum of exp -> reciprocal
__device__ float g_e [N_EDGES];           // exp(edge score)
__device__ half4 g_hsrc[N_NODES * D / 4]; // fp16 shadow of h_src (halves gather bytes)

// K1: per-node projections el/er, init s=0, out row = bias,
// and write the fp16 shadow copy of h_src. One warp per node.
__global__ void __launch_bounds__(256) k_node_proj(
    const float* __restrict__ h_src, const float* __restrict__ h_dst,
    const float* __restrict__ attn_l, const float* __restrict__ attn_r,
    const float* __restrict__ bias, float* __restrict__ out)
{
    int warp = (blockIdx.x * blockDim.x + threadIdx.x) >> 5;
    int lane = threadIdx.x & 31;
    if (warp >= N_NODES) return;

    float4 al = ((const float4*)attn_l)[lane];
    float4 ar = ((const float4*)attn_r)[lane];
    float4 x  = ((const float4*)h_src)[warp * 32 + lane];
    float4 y  = ((const float4*)h_dst)[warp * 32 + lane];

    float el = x.x*al.x + x.y*al.y + x.z*al.z + x.w*al.w;
    float er = y.x*ar.x + y.y*ar.y + y.z*ar.z + y.w*ar.w;
    #pragma unroll
    for (int o = 16; o; o >>= 1) {
        el += __shfl_xor_sync(0xFFFFFFFFu, el, o);
        er += __shfl_xor_sync(0xFFFFFFFFu, er, o);
    }

    // fp16 shadow: lane l holds floats [4l,4l+4) of the row -> 4 halves = 8B
    half4 packed;
    packed.a = __floats2half2_rn(x.x, x.y);
    packed.b = __floats2half2_rn(x.z, x.w);
    g_hsrc[warp * 32 + lane] = packed;

    // initialize output row with bias (out is poisoned before timing)
    float4 b = ((const float4*)bias)[lane];
    ((float4*)out)[warp * 32 + lane] = b;

    if (lane == 0) {
        g_el[warp] = el;
        g_er[warp] = er;
        g_s[warp]  = 0.0f;
    }
}

// K2: fused edge score + exp + segment sum, 4 edges per thread (MLP=4).
// exp(e)/sum == exp(e-m)/sum(exp(e-m)); e bounded, fp32-safe without max.
__global__ void __launch_bounds__(256) k_edge_exp(
    const int* __restrict__ esrc, const int* __restrict__ edst)
{
    int i = blockIdx.x * blockDim.x + threadIdx.x;
    if (i * 4 >= N_EDGES) return;
    int4 s4 = ((const int4*)esrc)[i];
    int4 d4 = ((const int4*)edst)[i];
    int s[4] = {s4.x, s4.y, s4.z, s4.w};
    int d[4] = {d4.x, d4.y, d4.z, d4.w};

    float el[4], er[4];
    #pragma unroll
    for (int j = 0; j < 4; j++) { el[j] = g_el[s[j]]; er[j] = g_er[d[j]]; }

    float a[4];
    #pragma unroll
    for (int j = 0; j < 4; j++) {
        float x = el[j] + er[j];
        float e = (x > 0.0f) ? x : NEG_SLOPE * x;
        a[j] = __expf(e);
    }
    ((float4*)g_e)[i] = make_float4(a[0], a[1], a[2], a[3]);
    #pragma unroll
    for (int j = 0; j < 4; j++) atomicAdd(&g_s[d[j]], a[j]);
}

// K3: per-node reciprocal of the softmax denominator.
__global__ void __launch_bounds__(256) k_recip()
{
    int i = blockIdx.x * blockDim.x + threadIdx.x;
    if (i >= N_NODES) return;
    g_s[i] = __frcp_rn(g_s[i]);
}

// K4: one warp per FOUR edges. fp16 row gathers (256B/row = half traffic),
// fp32 accumulation via RED.v4 fire-and-forget scatter-adds.
// Lane l gathers halves [4l,4l+4) (8B) and REDs floats [4l,4l+4) (16B).
__global__ void __launch_bounds__(256) k_aggregate(
    const int* __restrict__ esrc, const int* __restrict__ edst,
    float* __restrict__ out)
{
    int warp = (blockIdx.x * blockDim.x + threadIdx.x) >> 5;
    int lane = threadIdx.x & 31;
    if (warp * 4 >= N_EDGES) return;

    // broadcast loads: all lanes read the same 16B -> 1 wavefront each
    int4   s4 = ((const int4*)  esrc)[warp];
    int4   d4 = ((const int4*)  edst)[warp];
    float4 a4 = ((const float4*)g_e )[warp];

    int s[4] = {s4.x, s4.y, s4.z, s4.w};
    int d[4] = {d4.x, d4.y, d4.z, d4.w};
    float alpha[4];
    alpha[0] = a4.x * g_s[d[0]];
    alpha[1] = a4.y * g_s[d[1]];
    alpha[2] = a4.z * g_s[d[2]];
    alpha[3] = a4.w * g_s[d[3]];

    half4 raw[4];
    #pragma unroll
    for (int j = 0; j < 4; j++)
        raw[j] = g_hsrc[s[j] * 32 + lane];      // 4 independent 256B gathers

    #pragma unroll
    for (int j = 0; j < 4; j++) {
        float2 f0 = __half22float2(raw[j].a);
        float2 f1 = __half22float2(raw[j].b);
        float* dst = out + (size_t)d[j] * D + lane * 4;
        asm volatile("red.global.add.v4.f32 [%0], {%1, %2, %3, %4};"
                     :: "l"(dst),
                        "f"(f0.x * alpha[j]), "f"(f0.y * alpha[j]),
                        "f"(f1.x * alpha[j]), "f"(f1.y * alpha[j])
                     : "memory");
    }
}

extern "C" void kernel_launch(void* const* d_in, const int* in_sizes, int n_in,
                              void* d_out, int out_size)
{
    const float* h_src  = (const float*)d_in[0];
    const float* h_dst  = (const float*)d_in[1];
    const int*   esrc   = (const int*)  d_in[2];
    const int*   edst   = (const int*)  d_in[3];
    const float* attn_l = (const float*)d_in[4];
    const float* attn_r = (const float*)d_in[5];
    const float* bias   = (const float*)d_in[6];
    float* out = (float*)d_out;

    // K1: warp per node (+ fp16 shadow of h_src)
    k_node_proj<<<(N_NODES * 32 + 255) / 256, 256>>>(
        h_src, h_dst, attn_l, attn_r, bias, out);
    // K2: 4 edges per thread
    k_edge_exp<<<(N_EDGES / 4 + 255) / 256, 256>>>(esrc, edst);
    // K3: thread per node
    k_recip<<<(N_NODES + 255) / 256, 256>>>();
    // K4: warp per 4 edges, fp16 gathers
    k_aggregate<<<(N_EDGES / 4 * 32 + 255) / 256, 256>>>(esrc, edst, out);
}

// round 17
// speedup vs baseline: 1.1380x; 1.1380x over previous
#include <cuda_runtime.h>
#include <cuda_fp16.h>
#include <math.h>

#define N_NODES 100000
#define N_EDGES 1000000
#define D 128
#define NEG_SLOPE 0.01f
#define NB ((N_NODES + 255) / 256)   // 391 scan blocks

// 8-byte packet of 4 halves (one lane's slice of a row)
struct __align__(8) half4 { __half2 a, b; };
// packed (src id, exp score) per sorted edge
struct __align__(8) SA { int s; float a; };

// -------- scratch (device globals; no allocation allowed) --------
__device__ float g_el[N_NODES];
__device__ float g_er[N_NODES];
__device__ float g_s [N_NODES];           // 1 / per-dst sum of exp
__device__ int   g_count[N_NODES];        // in-degree histogram
__device__ int   g_bsum[NB];              // per-block count sums
__device__ int   g_boff[NB];              // exclusive block offsets
__device__ int   g_start[N_NODES + 1];    // CSR row offsets
__device__ int   g_off  [N_NODES];        // scatter cursors
__device__ SA    g_pse [N_EDGES];         // (src, exp) sorted by dst
__device__ int   g_pdst[N_EDGES];         // dst id, sorted
__device__ half4 g_hsrc[N_NODES * D / 4]; // fp16 shadow of h_src

// K1: node projections el/er, fp16 shadow, out=bias, zero histogram.
__global__ void __launch_bounds__(256) k_node_proj(
    const float* __restrict__ h_src, const float* __restrict__ h_dst,
    const float* __restrict__ attn_l, const float* __restrict__ attn_r,
    const float* __restrict__ bias, float* __restrict__ out)
{
    int warp = (blockIdx.x * blockDim.x + threadIdx.x) >> 5;
    int lane = threadIdx.x & 31;
    if (warp >= N_NODES) return;

    float4 al = ((const float4*)attn_l)[lane];
    float4 ar = ((const float4*)attn_r)[lane];
    float4 x  = ((const float4*)h_src)[warp * 32 + lane];
    float4 y  = ((const float4*)h_dst)[warp * 32 + lane];

    float el = x.x*al.x + x.y*al.y + x.z*al.z + x.w*al.w;
    float er = y.x*ar.x + y.y*ar.y + y.z*ar.z + y.w*ar.w;
    #pragma unroll
    for (int o = 16; o; o >>= 1) {
        el += __shfl_xor_sync(0xFFFFFFFFu, el, o);
        er += __shfl_xor_sync(0xFFFFFFFFu, er, o);
    }

    half4 packed;
    packed.a = __floats2half2_rn(x.x, x.y);
    packed.b = __floats2half2_rn(x.z, x.w);
    g_hsrc[warp * 32 + lane] = packed;

    float4 b = ((const float4*)bias)[lane];
    ((float4*)out)[warp * 32 + lane] = b;

    if (lane == 0) {
        g_el[warp] = el;
        g_er[warp] = er;
        g_count[warp] = 0;
    }
}

// K2: in-degree histogram, 4 edges per thread.
__global__ void __launch_bounds__(256) k_hist(const int* __restrict__ edst)
{
    int i = blockIdx.x * blockDim.x + threadIdx.x;
    if (i * 4 >= N_EDGES) return;
    int4 d4 = ((const int4*)edst)[i];
    atomicAdd(&g_count[d4.x], 1);
    atomicAdd(&g_count[d4.y], 1);
    atomicAdd(&g_count[d4.z], 1);
    atomicAdd(&g_count[d4.w], 1);
}

// K3a: per-256-block partial sums of g_count.
__global__ void __launch_bounds__(256) k_part()
{
    __shared__ int ws[8];
    int i = blockIdx.x * 256 + threadIdx.x;
    int c = (i < N_NODES) ? g_count[i] : 0;
    #pragma unroll
    for (int o = 16; o; o >>= 1) c += __shfl_xor_sync(0xFFFFFFFFu, c, o);
    if ((threadIdx.x & 31) == 0) ws[threadIdx.x >> 5] = c;
    __syncthreads();
    if (threadIdx.x == 0) {
        int s = 0;
        #pragma unroll
        for (int w = 0; w < 8; w++) s += ws[w];
        g_bsum[blockIdx.x] = s;
    }
}

// K3b: single-block exclusive scan of the NB block sums.
__global__ void __launch_bounds__(512) k_scan_blocks()
{
    __shared__ int ws[16];
    int tid = threadIdx.x, lane = tid & 31, wid = tid >> 5;
    int v = (tid < NB) ? g_bsum[tid] : 0;
    int x = v;
    #pragma unroll
    for (int o = 1; o < 32; o <<= 1) {
        int t = __shfl_up_sync(0xFFFFFFFFu, x, o);
        if (lane >= o) x += t;
    }
    if (lane == 31) ws[wid] = x;
    __syncthreads();
    if (wid == 0) {
        int w = (lane < 16) ? ws[lane] : 0;
        #pragma unroll
        for (int o = 1; o < 16; o <<= 1) {
            int t = __shfl_up_sync(0xFFFFFFFFu, w, o);
            if (lane >= o) w += t;
        }
        if (lane < 16) ws[lane] = w;
    }
    __syncthreads();
    int incl = x + (wid > 0 ? ws[wid - 1] : 0);
    if (tid < NB) g_boff[tid] = incl - v;          // exclusive
    if (tid == 0) g_start[N_NODES] = N_EDGES;
}

// K3c: block-local exclusive scan + block offset -> g_start / g_off.
__global__ void __launch_bounds__(256) k_start()
{
    __shared__ int ws[8];
    int i = blockIdx.x * 256 + threadIdx.x;
    int lane = threadIdx.x & 31, wid = threadIdx.x >> 5;
    int c = (i < N_NODES) ? g_count[i] : 0;
    int x = c;
    #pragma unroll
    for (int o = 1; o < 32; o <<= 1) {
        int t = __shfl_up_sync(0xFFFFFFFFu, x, o);
        if (lane >= o) x += t;
    }
    if (lane == 31) ws[wid] = x;
    __syncthreads();
    if (wid == 0 && lane < 8) {
        int w = ws[lane];
        #pragma unroll
        for (int o = 1; o < 8; o <<= 1) {
            int t = __shfl_up_sync(0xFFu, w, o);
            if (lane >= o) w += t;
        }
        ws[lane] = w;
    }
    __syncthreads();
    int excl = x - c + (wid > 0 ? ws[wid - 1] : 0) + g_boff[blockIdx.x];
    if (i < N_NODES) {
        g_start[i] = excl;
        g_off[i]   = excl;
    }
}

// K4: edge score + exp, scatter into dst-sorted order.
__global__ void __launch_bounds__(256) k_scatter(
    const int* __restrict__ esrc, const int* __restrict__ edst)
{
    int i = blockIdx.x * blockDim.x + threadIdx.x;
    if (i >= N_EDGES) return;
    int s = esrc[i];
    int d = edst[i];
    float x = g_el[s] + g_er[d];
    float e = (x > 0.0f) ? x : NEG_SLOPE * x;
    // exp(e)/sum == exp(e-m)/sum(exp(e-m)); e bounded, fp32-safe
    float a = __expf(e);
    int pos = atomicAdd(&g_off[d], 1);
    SA t; t.s = s; t.a = a;
    g_pse[pos]  = t;
    g_pdst[pos] = d;
}

// K5: per-node softmax denominator from the sorted exp values (contiguous
// reads, no atomics), store reciprocal.
__global__ void __launch_bounds__(256) k_segsum()
{
    int n = blockIdx.x * blockDim.x + threadIdx.x;
    if (n >= N_NODES) return;
    int beg = g_start[n];
    int end = g_start[n + 1];
    float s = 0.0f;
    for (int i = beg; i < end; i++) s += g_pse[i].a;
    g_s[n] = (end > beg) ? __frcp_rn(s) : 0.0f;
}

// K6: one warp per EIGHT dst-sorted edges. fp16 row gathers, register-combine
// runs of equal dst (E[distinct]=1.7 per window), then RED.v4 per run.
__global__ void __launch_bounds__(256) k_aggregate(float* __restrict__ out)
{
    int warp = (blockIdx.x * blockDim.x + threadIdx.x) >> 5;
    int lane = threadIdx.x & 31;
    if (warp * 8 >= N_EDGES) return;

    // broadcast loads (uniform across lanes)
    const int4* pse4 = (const int4*)g_pse;    // 2 edges per int4
    int4 p0 = pse4[warp * 4 + 0];
    int4 p1 = pse4[warp * 4 + 1];
    int4 p2 = pse4[warp * 4 + 2];
    int4 p3 = pse4[warp * 4 + 3];
    int4 d0 = ((const int4*)g_pdst)[warp * 2 + 0];
    int4 d1 = ((const int4*)g_pdst)[warp * 2 + 1];

    int s[8] = {p0.x, p0.z, p1.x, p1.z, p2.x, p2.z, p3.x, p3.z};
    float a[8] = {__int_as_float(p0.y), __int_as_float(p0.w),
                  __int_as_float(p1.y), __int_as_float(p1.w),
                  __int_as_float(p2.y), __int_as_float(p2.w),
                  __int_as_float(p3.y), __int_as_float(p3.w)};
    int d[8] = {d0.x, d0.y, d0.z, d0.w, d1.x, d1.y, d1.z, d1.w};

    float alpha[8];
    #pragma unroll
    for (int j = 0; j < 8; j++) alpha[j] = a[j] * g_s[d[j]];

    half4 raw[8];
    #pragma unroll
    for (int j = 0; j < 8; j++)
        raw[j] = g_hsrc[s[j] * 32 + lane];     // 8 independent 256B gathers

    float4 val[8];
    #pragma unroll
    for (int j = 0; j < 8; j++) {
        float2 f0 = __half22float2(raw[j].a);
        float2 f1 = __half22float2(raw[j].b);
        val[j] = make_float4(f0.x * alpha[j], f0.y * alpha[j],
                             f1.x * alpha[j], f1.y * alpha[j]);
    }

    // merge runs of equal dst (uniform branch: d[] identical across lanes)
    float4 acc = val[0];
    int cur = d[0];
    #pragma unroll
    for (int j = 1; j < 8; j++) {
        if (d[j] == cur) {
            acc.x += val[j].x; acc.y += val[j].y;
            acc.z += val[j].z; acc.w += val[j].w;
        } else {
            float* dst = out + (size_t)cur * D + lane * 4;
            asm volatile("red.global.add.v4.f32 [%0], {%1, %2, %3, %4};"
                         :: "l"(dst), "f"(acc.x), "f"(acc.y),
                            "f"(acc.z), "f"(acc.w) : "memory");
            acc = val[j];
            cur = d[j];
        }
    }
    float* dst = out + (size_t)cur * D + lane * 4;
    asm volatile("red.global.add.v4.f32 [%0], {%1, %2, %3, %4};"
                 :: "l"(dst), "f"(acc.x), "f"(acc.y),
                    "f"(acc.z), "f"(acc.w) : "memory");
}

extern "C" void kernel_launch(void* const* d_in, const int* in_sizes, int n_in,
                              void* d_out, int out_size)
{
    const float* h_src  = (const float*)d_in[0];
    const float* h_dst  = (const float*)d_in[1];
    const int*   esrc   = (const int*)  d_in[2];
    const int*   edst   = (const int*)  d_in[3];
    const float* attn_l = (const float*)d_in[4];
    const float* attn_r = (const float*)d_in[5];
    const float* bias   = (const float*)d_in[6];
    float* out = (float*)d_out;

    k_node_proj<<<(N_NODES * 32 + 255) / 256, 256>>>(
        h_src, h_dst, attn_l, attn_r, bias, out);
    k_hist<<<(N_EDGES / 4 + 255) / 256, 256>>>(edst);
    k_part<<<NB, 256>>>();
    k_scan_blocks<<<1, 512>>>();
    k_start<<<NB, 256>>>();
    k_scatter<<<(N_EDGES + 255) / 256, 256>>>(esrc, edst);
    k_segsum<<<(N_NODES + 255) / 256, 256>>>();
    k_aggregate<<<(N_EDGES / 8 * 32 + 255) / 256, 256>>>(out);
}